// round 2
// baseline (speedup 1.0000x reference)
#include <cuda_runtime.h>
#include <math.h>

#define N_ROWS 4096
#define F_DIM  4096
#define C_CLS  20
#define KC     32
#define KSPLIT 4
#define KLEN   (F_DIM / KSPLIT)

typedef unsigned long long ull;

// ---------------- scratch (static device arrays; no allocation) ----------------
__device__ float g_Wpack[F_DIM * 64];           // [W_cls(20) | W_r1(21) | W_r2(21) | pad2]
__device__ float g_bpack[64];
__device__ float g_WdetP[F_DIM * 32];           // W_det padded to 32 cols
__device__ float g_Spart[KSPLIT * N_ROWS * 64]; // split-K partials (roi)
__device__ float g_Dpart[KSPLIT * N_ROWS * 32]; // split-K partials (det)
__device__ float g_S[N_ROWS * 64];              // scores: cls 0-19, r1 20-40, r2 41-61
__device__ float g_P[N_ROWS * 64];              // row-softmax probs, same layout
__device__ float g_D[N_ROWS * 32];              // det scores (cols 0-19 valid)
__device__ float g_dcs[C_CLS];                  // det_cls_score
__device__ int   g_midx[64];                    // maxidx1 at [0..19], maxidx2 at [32..51]
__device__ float g_boxes[2 * C_CLS * 5];        // per-sup per-class: x1,y1,x2,y2,area
__device__ float g_part4[16 * 4];               // per-block loss partials

// ---------------- f32x2 helpers ----------------
__device__ __forceinline__ ull pack2(float x, float y) {
    ull r; asm("mov.b64 %0, {%1,%2};" : "=l"(r) : "f"(x), "f"(y)); return r;
}
__device__ __forceinline__ void unpack2(ull v, float& x, float& y) {
    asm("mov.b64 {%0,%1}, %2;" : "=f"(x), "=f"(y) : "l"(v));
}
__device__ __forceinline__ void ffma2(ull& d, ull a, ull b) {
    asm("fma.rn.f32x2 %0, %1, %2, %0;" : "+l"(d) : "l"(a), "l"(b));
}

// ---------------- weight packing ----------------
__global__ void pack_kernel(const float* __restrict__ Wc, const float* __restrict__ Wd,
                            const float* __restrict__ W1, const float* __restrict__ W2,
                            const float* __restrict__ bc, const float* __restrict__ b1,
                            const float* __restrict__ b2) {
    int k = blockIdx.x;   // 0..4095
    int c = threadIdx.x;  // 0..63
    float w;
    if      (c < 20) w = Wc[k * 20 + c];
    else if (c < 41) w = W1[k * 21 + (c - 20)];
    else if (c < 62) w = W2[k * 21 + (c - 41)];
    else             w = 0.f;
    g_Wpack[k * 64 + c] = w;
    if (c < 32) g_WdetP[k * 32 + c] = (c < 20) ? Wd[k * 20 + c] : 0.f;
    if (k == 0) {
        float b;
        if      (c < 20) b = bc[c];
        else if (c < 41) b = b1[c - 20];
        else if (c < 62) b = b2[c - 41];
        else             b = 0.f;
        g_bpack[c] = b;
    }
}

// ---------------- fused skinny GEMM (fp32, f32x2 packed FMA, split-K) ----------------
// block: 256 threads = 32 col-lanes x 8 row-groups; tile 64 rows x TN cols
template<int TN, bool DIFF, bool ROI>
__global__ void __launch_bounds__(256) gemm_kernel(const float* __restrict__ A,
                                                   const float* __restrict__ A2) {
    __shared__ __align__(16) float As[KC][66];   // [kk][row]; 66 keeps even-idx pairs 8B-aligned
    __shared__ __align__(16) float Ws[KC][TN];   // [kk][col]
    const float* __restrict__ W = ROI ? g_Wpack : g_WdetP;
    float* __restrict__ out = (ROI ? g_Spart : g_Dpart) + (size_t)blockIdx.y * (N_ROWS * TN);
    const int tid  = threadIdx.x;
    const int lane = tid & 31;
    const int rg   = tid >> 5;
    const int row0 = blockIdx.x * 64;
    const int kbase = blockIdx.y * KLEN;

    ull acc[4][TN / 32];
#pragma unroll
    for (int p = 0; p < 4; p++)
#pragma unroll
        for (int j = 0; j < TN / 32; j++) acc[p][j] = 0ull;

    for (int kc = 0; kc < KLEN; kc += KC) {
        const int k0 = kbase + kc;
        // stage A (transposed): 64 rows x KC, coalesced float4 along k
        for (int i = tid; i < 64 * KC / 4; i += 256) {
            int r = i >> 3, kq = (i & 7) << 2;
            float4 v = *(const float4*)&A[(size_t)(row0 + r) * F_DIM + k0 + kq];
            if (DIFF) {
                float4 u = *(const float4*)&A2[(size_t)(row0 + r) * F_DIM + k0 + kq];
                v.x -= u.x; v.y -= u.y; v.z -= u.z; v.w -= u.w;
            }
            As[kq + 0][r] = v.x; As[kq + 1][r] = v.y;
            As[kq + 2][r] = v.z; As[kq + 3][r] = v.w;
        }
        // stage W: contiguous [KC][TN]
        for (int i = tid; i < KC * TN / 4; i += 256)
            ((float4*)Ws)[i] = ((const float4*)(W + (size_t)k0 * TN))[i];
        __syncthreads();

#pragma unroll
        for (int kk = 0; kk < KC; kk++) {
            ull a2[4];
#pragma unroll
            for (int p = 0; p < 4; p++) {
                float2 av = *(const float2*)&As[kk][rg * 8 + p * 2];  // broadcast in warp
                a2[p] = pack2(av.x, av.y);
            }
#pragma unroll
            for (int j = 0; j < TN / 32; j++) {
                float w = Ws[kk][lane + 32 * j];
                ull w2 = pack2(w, w);
#pragma unroll
                for (int p = 0; p < 4; p++) ffma2(acc[p][j], a2[p], w2);
            }
        }
        __syncthreads();
    }
#pragma unroll
    for (int p = 0; p < 4; p++) {
        int r = row0 + rg * 8 + p * 2;
#pragma unroll
        for (int j = 0; j < TN / 32; j++) {
            float lo, hi; unpack2(acc[p][j], lo, hi);
            out[(size_t)r * TN + lane + 32 * j]       = lo;
            out[(size_t)(r + 1) * TN + lane + 32 * j] = hi;
        }
    }
}

// ---------------- split-K reduce + bias ----------------
__global__ void reduce_kernel() {
    int idx = blockIdx.x * 256 + threadIdx.x;  // grid covers N*64
    if (idx < N_ROWS * 64) {
        float s = g_bpack[idx & 63];
#pragma unroll
        for (int k = 0; k < KSPLIT; k++) s += g_Spart[k * N_ROWS * 64 + idx];
        g_S[idx] = s;
    }
    if (idx < N_ROWS * 32) {
        float s = 0.f;  // det biases cancel: (f@W+b)-(c@W+b) = (f-c)@W
#pragma unroll
        for (int k = 0; k < KSPLIT; k++) s += g_Dpart[k * N_ROWS * 32 + idx];
        g_D[idx] = s;
    }
}

// ---------------- row softmaxes (cls / r1 / r2) ----------------
__global__ void rowsoft_kernel() {
    int n = blockIdx.x * 256 + threadIdx.x;
    if (n >= N_ROWS) return;
    float v[64];
    const float4* src = (const float4*)(g_S + (size_t)n * 64);
#pragma unroll
    for (int i = 0; i < 16; i++) {
        float4 t = src[i];
        v[i * 4] = t.x; v[i * 4 + 1] = t.y; v[i * 4 + 2] = t.z; v[i * 4 + 3] = t.w;
    }
    float* outp = g_P + (size_t)n * 64;
    const int off0[3] = {0, 20, 41};
    const int len0[3] = {20, 21, 21};
#pragma unroll
    for (int s = 0; s < 3; s++) {
        float m = -1e30f;
#pragma unroll
        for (int i = 0; i < 21; i++) if (i < len0[s]) m = fmaxf(m, v[off0[s] + i]);
        float se = 0.f;
#pragma unroll
        for (int i = 0; i < 21; i++) if (i < len0[s]) se += expf(v[off0[s] + i] - m);
        float inv = 1.f / se;
#pragma unroll
        for (int i = 0; i < 21; i++) if (i < len0[s]) outp[off0[s] + i] = expf(v[off0[s] + i] - m) * inv;
    }
}

// ---------------- per-class column kernel: det softmax stats + det_cls_score + argmaxes ----------------
__global__ void colstats_kernel(const float* __restrict__ ISw) {
    int c = blockIdx.x, tid = threadIdx.x;
    __shared__ float sf[256];
    __shared__ int   si[256];
    // pass 1: column max of det score
    float m = -1e30f;
    for (int n = tid; n < N_ROWS; n += 256) m = fmaxf(m, g_D[n * 32 + c]);
    sf[tid] = m; __syncthreads();
    for (int st = 128; st; st >>= 1) { if (tid < st) sf[tid] = fmaxf(sf[tid], sf[tid + st]); __syncthreads(); }
    m = sf[0]; __syncthreads();
    // pass 2: sum exp
    float se = 0.f;
    for (int n = tid; n < N_ROWS; n += 256) se += expf(g_D[n * 32 + c] - m);
    sf[tid] = se; __syncthreads();
    for (int st = 128; st; st >>= 1) { if (tid < st) sf[tid] += sf[tid + st]; __syncthreads(); }
    se = sf[0]; __syncthreads();
    float inv = 1.f / se;
    // pass 3: det_cls_score + argmax(p1), argmax(p2) with first-max semantics
    float dcs = 0.f;
    float v1 = -1e30f; int i1 = N_ROWS;
    float v2 = -1e30f; int i2 = N_ROWS;
    for (int n = tid; n < N_ROWS; n += 256) {
        float dp = expf(g_D[n * 32 + c] - m) * inv;
        float w  = ISw[n];
        dcs += g_S[n * 64 + c] * dp;
        float p1 = g_P[n * 64 + c] * dp * w;          // cls_prob * det_prob * ISw
        if (p1 > v1) { v1 = p1; i1 = n; }
        float p2 = g_P[n * 64 + 21 + c] * w;          // refine_prob_1[:,1:] * ISw
        if (p2 > v2) { v2 = p2; i2 = n; }
    }
    sf[tid] = dcs; __syncthreads();
    for (int st = 128; st; st >>= 1) { if (tid < st) sf[tid] += sf[tid + st]; __syncthreads(); }
    if (tid == 0) g_dcs[c] = sf[0];
    __syncthreads();
    // argmax1 (tie -> smaller index == first occurrence)
    sf[tid] = v1; si[tid] = i1; __syncthreads();
    for (int st = 128; st; st >>= 1) {
        if (tid < st) {
            float ov = sf[tid + st]; int oi = si[tid + st];
            if (ov > sf[tid] || (ov == sf[tid] && oi < si[tid])) { sf[tid] = ov; si[tid] = oi; }
        }
        __syncthreads();
    }
    if (tid == 0) g_midx[c] = si[0];
    __syncthreads();
    // argmax2
    sf[tid] = v2; si[tid] = i2; __syncthreads();
    for (int st = 128; st; st >>= 1) {
        if (tid < st) {
            float ov = sf[tid + st]; int oi = si[tid + st];
            if (ov > sf[tid] || (ov == sf[tid] && oi < si[tid])) { sf[tid] = ov; si[tid] = oi; }
        }
        __syncthreads();
    }
    if (tid == 0) g_midx[32 + c] = si[0];
}

// ---------------- gather selected boxes ----------------
__global__ void boxes_kernel(const float* __restrict__ ss) {
    int t = threadIdx.x;
    if (t < 2 * C_CLS) {
        int s = t / C_CLS, c = t % C_CLS;
        int idx = g_midx[s * 32 + c];
        float x1 = ss[idx * 5 + 1], y1 = ss[idx * 5 + 2];
        float x2 = ss[idx * 5 + 3], y2 = ss[idx * 5 + 4];
        float* b = g_boxes + t * 5;
        b[0] = x1; b[1] = y1; b[2] = x2; b[3] = y2;
        b[4] = (x2 - x1 + 1.f) * (y2 - y1 + 1.f);
    }
}

// ---------------- IoU supervision + loss partials ----------------
__global__ void suploss_kernel(const float* __restrict__ ss, const float* __restrict__ ISw,
                               const int* __restrict__ lab) {
    __shared__ float sb[2 * C_CLS * 5];
    __shared__ int   sl[C_CLS];
    __shared__ float red[256];
    int tid = threadIdx.x;
    if (tid < 2 * C_CLS * 5) sb[tid] = g_boxes[tid];
    if (tid < C_CLS)         sl[tid] = lab[tid];
    __syncthreads();

    int n = blockIdx.x * 256 + tid;
    float bx1 = ss[n * 5 + 1], by1 = ss[n * 5 + 2];
    float bx2 = ss[n * 5 + 3], by2 = ss[n * 5 + 4];
    float ab = (bx2 - bx1 + 1.f) * (by2 - by1 + 1.f);
    float w  = ISw[n];
    float res[4];
#pragma unroll
    for (int s = 0; s < 2; s++) {
        float mo = -1e30f; int gt = 0;
#pragma unroll
        for (int c = 0; c < C_CLS; c++) {
            const float* q = sb + (s * C_CLS + c) * 5;
            float ix1 = fmaxf(bx1, q[0]), iy1 = fmaxf(by1, q[1]);
            float ix2 = fminf(bx2, q[2]), iy2 = fminf(by2, q[3]);
            float iw = fmaxf(ix2 - ix1 + 1.f, 0.f), ih = fmaxf(iy2 - iy1 + 1.f, 0.f);
            float inter = iw * ih;
            float ov = (sl[c] == 1) ? inter / (ab + q[4] - inter) : -1.f;
            if (ov > mo) { mo = ov; gt = c; }
        }
        bool fg = mo > 0.5f;
        bool bg = (mo >= 0.1f) && (mo < 0.5f);
        bool keep = fg || bg;
        int col = fg ? gt + 1 : 0;
        int base = (s == 0) ? 20 : 41;   // refine_prob_1 / refine_prob_2
        float lp = logf(g_P[(size_t)n * 64 + base + col]);
        res[s * 2]     = keep ? 1.f : 0.f;
        res[s * 2 + 1] = keep ? w * lp : 0.f;
    }
#pragma unroll
    for (int j = 0; j < 4; j++) {
        red[tid] = res[j]; __syncthreads();
        for (int st = 128; st; st >>= 1) { if (tid < st) red[tid] += red[tid + st]; __syncthreads(); }
        if (tid == 0) g_part4[blockIdx.x * 4 + j] = red[0];
        __syncthreads();
    }
}

// ---------------- final combine ----------------
__global__ void final_kernel(const int* __restrict__ lab, float* __restrict__ out) {
    if (threadIdx.x != 0) return;
    float c1 = 0, s1 = 0, c2 = 0, s2 = 0;
    for (int b = 0; b < 16; b++) {
        c1 += g_part4[b * 4 + 0]; s1 += g_part4[b * 4 + 1];
        c2 += g_part4[b * 4 + 2]; s2 += g_part4[b * 4 + 3];
    }
    float h = 0.f;
    for (int c = 0; c < C_CLS; c++) h += fmaxf(0.f, 1.f - (float)lab[c] * g_dcs[c]);
    float loss = h / (float)C_CLS + 0.1f * (-s1 / c1) + 0.1f * (-s2 / c2);
    out[0] = loss;
}

// ---------------- launch ----------------
extern "C" void kernel_launch(void* const* d_in, const int* in_sizes, int n_in,
                              void* d_out, int out_size) {
    const float* roi = (const float*)d_in[0];
    const float* ctx = (const float*)d_in[1];
    const float* frm = (const float*)d_in[2];
    const float* Wc  = (const float*)d_in[3];
    const float* bc  = (const float*)d_in[4];
    const float* Wd  = (const float*)d_in[5];
    // d_in[6] = b_det: cancels analytically in det_score
    const float* W1  = (const float*)d_in[7];
    const float* b1  = (const float*)d_in[8];
    const float* W2  = (const float*)d_in[9];
    const float* b2  = (const float*)d_in[10];
    const float* ss  = (const float*)d_in[11];
    const float* isw = (const float*)d_in[12];
    const int*   lab = (const int*)d_in[13];
    float* out = (float*)d_out;

    pack_kernel<<<F_DIM, 64>>>(Wc, Wd, W1, W2, bc, b1, b2);
    gemm_kernel<64, false, true ><<<dim3(64, KSPLIT), 256>>>(roi, nullptr);
    gemm_kernel<32, true,  false><<<dim3(64, KSPLIT), 256>>>(frm, ctx);
    reduce_kernel<<<N_ROWS * 64 / 256, 256>>>();
    rowsoft_kernel<<<16, 256>>>();
    colstats_kernel<<<C_CLS, 256>>>(isw);
    boxes_kernel<<<1, 64>>>(ss);
    suploss_kernel<<<16, 256>>>(ss, isw, lab);
    final_kernel<<<1, 32>>>(lab, out);
}

// round 3
// speedup vs baseline: 2.2203x; 2.2203x over previous
#include <cuda_runtime.h>
#include <math.h>

#define N_ROWS 4096
#define F_DIM  4096
#define C_CLS  20
#define KC     32
#define KSPLIT 8
#define KLEN   (F_DIM / KSPLIT)

// ---------------- scratch (static device arrays; no allocation) ----------------
__device__ float g_Wpack[F_DIM * 64];           // [W_cls(20) | W_r1(21) | W_r2(21) | pad2], tf32-rounded
__device__ float g_bpack[64];
__device__ float g_WdetP[F_DIM * 32];           // W_det padded to 32 cols, tf32-rounded
__device__ float g_Spart[KSPLIT * N_ROWS * 64]; // split-K partials (roi)
__device__ float g_Dpart[KSPLIT * N_ROWS * 32]; // split-K partials (det)
__device__ float g_S[N_ROWS * 64];              // scores: cls 0-19, r1 20-40, r2 41-61
__device__ float g_P[N_ROWS * 64];              // row-softmax probs, same layout
__device__ float g_D[N_ROWS * 32];              // det scores (cols 0-19 valid)
__device__ float g_dcs[C_CLS];                  // det_cls_score
__device__ int   g_midx[64];                    // maxidx1 at [0..19], maxidx2 at [32..51]
__device__ float g_boxes[2 * C_CLS * 5];        // per-sup per-class: x1,y1,x2,y2,area
__device__ float g_part4[16 * 4];               // per-block loss partials

// ---------------- helpers ----------------
__device__ __forceinline__ float tf32r(float x) {
    unsigned r; asm("cvt.rna.tf32.f32 %0, %1;" : "=r"(r) : "f"(x));
    return __uint_as_float(r);
}
__device__ __forceinline__ void mma_tf32(float* c, const unsigned* a, const unsigned* b) {
    asm("mma.sync.aligned.m16n8k8.row.col.f32.tf32.tf32.f32 "
        "{%0,%1,%2,%3}, {%4,%5,%6,%7}, {%8,%9}, {%0,%1,%2,%3};"
        : "+f"(c[0]), "+f"(c[1]), "+f"(c[2]), "+f"(c[3])
        : "r"(a[0]), "r"(a[1]), "r"(a[2]), "r"(a[3]), "r"(b[0]), "r"(b[1]));
}

// ---------------- weight packing (+ tf32 rounding of weights) ----------------
__global__ void pack_kernel(const float* __restrict__ Wc, const float* __restrict__ Wd,
                            const float* __restrict__ W1, const float* __restrict__ W2,
                            const float* __restrict__ bc, const float* __restrict__ b1,
                            const float* __restrict__ b2) {
    int k = blockIdx.x;   // 0..4095
    int c = threadIdx.x;  // 0..63
    float w;
    if      (c < 20) w = Wc[k * 20 + c];
    else if (c < 41) w = W1[k * 21 + (c - 20)];
    else if (c < 62) w = W2[k * 21 + (c - 41)];
    else             w = 0.f;
    g_Wpack[k * 64 + c] = tf32r(w);
    if (c < 32) g_WdetP[k * 32 + c] = (c < 20) ? tf32r(Wd[k * 20 + c]) : 0.f;
    if (k == 0) {
        float b;
        if      (c < 20) b = bc[c];
        else if (c < 41) b = b1[c - 20];
        else if (c < 62) b = b2[c - 41];
        else             b = 0.f;
        g_bpack[c] = b;
    }
}

// ---------------- tf32 tensor-core GEMM, split-K, reg-prefetch double buffer ----------------
// block 256 thr = 8 warps: wm = warp&3 (32 rows each, TM=128), wn = warp>>2 (TN/2 cols each)
template<int TN, bool DIFF, bool ROI>
__global__ void __launch_bounds__(256, 2) gemm_tf32(const float* __restrict__ A,
                                                    const float* __restrict__ A2) {
    constexpr int TM   = 128;
    constexpr int PADA = 36;        // bank = 4g + t : conflict-free frag loads
    constexpr int PADW = TN + 8;    // bank = 8t + g : conflict-free frag loads
    constexpr int NT   = TN / 16;   // n-tiles per warp (per wn half)
    constexpr int WREG = (KC * TN) / 1024;  // float4 per thread for W stage

    __shared__ __align__(16) float As[TM][PADA];
    __shared__ __align__(16) float Ws[KC][PADW];

    const float* __restrict__ W = ROI ? g_Wpack : g_WdetP;
    float* __restrict__ out = (ROI ? g_Spart : g_Dpart) + (size_t)blockIdx.y * (N_ROWS * TN);

    const int tid  = threadIdx.x;
    const int warp = tid >> 5;
    const int lane = tid & 31;
    const int g    = lane >> 2;
    const int t    = lane & 3;
    const int wm   = warp & 3;
    const int wn   = warp >> 2;
    const int row0 = blockIdx.x * TM;
    const int kbase = blockIdx.y * KLEN;

    float acc[2][NT][4];
#pragma unroll
    for (int mt = 0; mt < 2; mt++)
#pragma unroll
        for (int nt = 0; nt < NT; nt++)
#pragma unroll
            for (int q = 0; q < 4; q++) acc[mt][nt][q] = 0.f;

    float4 rA[4];
    float4 rW[WREG];

    auto loadA = [&](int kc) {
#pragma unroll
        for (int p = 0; p < 4; p++) {
            int i = p * 256 + tid;
            int r = i >> 3, kq = (i & 7) << 2;
            float4 v = *(const float4*)&A[(size_t)(row0 + r) * F_DIM + kbase + kc + kq];
            if (DIFF) {
                float4 u = *(const float4*)&A2[(size_t)(row0 + r) * F_DIM + kbase + kc + kq];
                v.x -= u.x; v.y -= u.y; v.z -= u.z; v.w -= u.w;
            }
            rA[p] = v;
        }
    };
    auto loadW = [&](int kc) {
#pragma unroll
        for (int p = 0; p < WREG; p++) {
            int i = p * 256 + tid;
            int kr = i / (TN / 4), nc = (i % (TN / 4)) * 4;
            rW[p] = *(const float4*)&W[(size_t)(kbase + kc + kr) * TN + nc];
        }
    };
    auto stage = [&]() {
#pragma unroll
        for (int p = 0; p < 4; p++) {
            int i = p * 256 + tid;
            int r = i >> 3, kq = (i & 7) << 2;
            As[r][kq + 0] = tf32r(rA[p].x); As[r][kq + 1] = tf32r(rA[p].y);
            As[r][kq + 2] = tf32r(rA[p].z); As[r][kq + 3] = tf32r(rA[p].w);
        }
#pragma unroll
        for (int p = 0; p < WREG; p++) {
            int i = p * 256 + tid;
            int kr = i / (TN / 4), nc = (i % (TN / 4)) * 4;
            Ws[kr][nc + 0] = rW[p].x; Ws[kr][nc + 1] = rW[p].y;
            Ws[kr][nc + 2] = rW[p].z; Ws[kr][nc + 3] = rW[p].w;
        }
    };

    loadA(0); loadW(0);
    for (int kc = 0; kc < KLEN; kc += KC) {
        stage();
        __syncthreads();
        if (kc + KC < KLEN) { loadA(kc + KC); loadW(kc + KC); }  // overlap with MMAs
#pragma unroll
        for (int k8 = 0; k8 < KC / 8; k8++) {
            const int kb = k8 * 8;
            unsigned a[2][4];
#pragma unroll
            for (int mt = 0; mt < 2; mt++) {
                int rb = wm * 32 + mt * 16;
                a[mt][0] = __float_as_uint(As[rb + g][kb + t]);
                a[mt][1] = __float_as_uint(As[rb + g + 8][kb + t]);
                a[mt][2] = __float_as_uint(As[rb + g][kb + t + 4]);
                a[mt][3] = __float_as_uint(As[rb + g + 8][kb + t + 4]);
            }
            unsigned b[NT][2];
#pragma unroll
            for (int nt = 0; nt < NT; nt++) {
                int nb = wn * (TN / 2) + nt * 8;
                b[nt][0] = __float_as_uint(Ws[kb + t][nb + g]);
                b[nt][1] = __float_as_uint(Ws[kb + t + 4][nb + g]);
            }
#pragma unroll
            for (int mt = 0; mt < 2; mt++)
#pragma unroll
                for (int nt = 0; nt < NT; nt++) mma_tf32(acc[mt][nt], a[mt], b[nt]);
        }
        __syncthreads();
    }

    // epilogue: c0,c1 at (row g, cols 2t,2t+1), c2,c3 at row g+8
#pragma unroll
    for (int mt = 0; mt < 2; mt++) {
        int r = row0 + wm * 32 + mt * 16 + g;
#pragma unroll
        for (int nt = 0; nt < NT; nt++) {
            int cn = wn * (TN / 2) + nt * 8 + 2 * t;
            *(float2*)&out[(size_t)r * TN + cn]       = make_float2(acc[mt][nt][0], acc[mt][nt][1]);
            *(float2*)&out[(size_t)(r + 8) * TN + cn] = make_float2(acc[mt][nt][2], acc[mt][nt][3]);
        }
    }
}

// ---------------- split-K reduce + bias ----------------
__global__ void reduce_kernel() {
    int idx = blockIdx.x * 256 + threadIdx.x;  // grid covers N*64
    if (idx < N_ROWS * 64) {
        float s = g_bpack[idx & 63];
#pragma unroll
        for (int k = 0; k < KSPLIT; k++) s += g_Spart[k * N_ROWS * 64 + idx];
        g_S[idx] = s;
    }
    if (idx < N_ROWS * 32) {
        float s = 0.f;  // det biases cancel: (f@W+b)-(c@W+b) = (f-c)@W
#pragma unroll
        for (int k = 0; k < KSPLIT; k++) s += g_Dpart[k * N_ROWS * 32 + idx];
        g_D[idx] = s;
    }
}

// ---------------- row softmaxes (cls / r1 / r2) ----------------
__global__ void rowsoft_kernel() {
    int n = blockIdx.x * 256 + threadIdx.x;
    if (n >= N_ROWS) return;
    float v[64];
    const float4* src = (const float4*)(g_S + (size_t)n * 64);
#pragma unroll
    for (int i = 0; i < 16; i++) {
        float4 t = src[i];
        v[i * 4] = t.x; v[i * 4 + 1] = t.y; v[i * 4 + 2] = t.z; v[i * 4 + 3] = t.w;
    }
    float* outp = g_P + (size_t)n * 64;
    const int off0[3] = {0, 20, 41};
    const int len0[3] = {20, 21, 21};
#pragma unroll
    for (int s = 0; s < 3; s++) {
        float m = -1e30f;
#pragma unroll
        for (int i = 0; i < 21; i++) if (i < len0[s]) m = fmaxf(m, v[off0[s] + i]);
        float se = 0.f;
#pragma unroll
        for (int i = 0; i < 21; i++) if (i < len0[s]) se += expf(v[off0[s] + i] - m);
        float inv = 1.f / se;
#pragma unroll
        for (int i = 0; i < 21; i++) if (i < len0[s]) outp[off0[s] + i] = expf(v[off0[s] + i] - m) * inv;
    }
}

// ---------------- per-class column kernel: det softmax stats + det_cls_score + argmaxes ----------------
__global__ void colstats_kernel(const float* __restrict__ ISw) {
    int c = blockIdx.x, tid = threadIdx.x;
    __shared__ float sf[256];
    __shared__ int   si[256];
    float m = -1e30f;
    for (int n = tid; n < N_ROWS; n += 256) m = fmaxf(m, g_D[n * 32 + c]);
    sf[tid] = m; __syncthreads();
    for (int st = 128; st; st >>= 1) { if (tid < st) sf[tid] = fmaxf(sf[tid], sf[tid + st]); __syncthreads(); }
    m = sf[0]; __syncthreads();
    float se = 0.f;
    for (int n = tid; n < N_ROWS; n += 256) se += expf(g_D[n * 32 + c] - m);
    sf[tid] = se; __syncthreads();
    for (int st = 128; st; st >>= 1) { if (tid < st) sf[tid] += sf[tid + st]; __syncthreads(); }
    se = sf[0]; __syncthreads();
    float inv = 1.f / se;
    float dcs = 0.f;
    float v1 = -1e30f; int i1 = N_ROWS;
    float v2 = -1e30f; int i2 = N_ROWS;
    for (int n = tid; n < N_ROWS; n += 256) {
        float dp = expf(g_D[n * 32 + c] - m) * inv;
        float w  = ISw[n];
        dcs += g_S[n * 64 + c] * dp;
        float p1 = g_P[n * 64 + c] * dp * w;          // cls_prob * det_prob * ISw
        if (p1 > v1) { v1 = p1; i1 = n; }
        float p2 = g_P[n * 64 + 21 + c] * w;          // refine_prob_1[:,1:] * ISw
        if (p2 > v2) { v2 = p2; i2 = n; }
    }
    sf[tid] = dcs; __syncthreads();
    for (int st = 128; st; st >>= 1) { if (tid < st) sf[tid] += sf[tid + st]; __syncthreads(); }
    if (tid == 0) g_dcs[c] = sf[0];
    __syncthreads();
    sf[tid] = v1; si[tid] = i1; __syncthreads();
    for (int st = 128; st; st >>= 1) {
        if (tid < st) {
            float ov = sf[tid + st]; int oi = si[tid + st];
            if (ov > sf[tid] || (ov == sf[tid] && oi < si[tid])) { sf[tid] = ov; si[tid] = oi; }
        }
        __syncthreads();
    }
    if (tid == 0) g_midx[c] = si[0];
    __syncthreads();
    sf[tid] = v2; si[tid] = i2; __syncthreads();
    for (int st = 128; st; st >>= 1) {
        if (tid < st) {
            float ov = sf[tid + st]; int oi = si[tid + st];
            if (ov > sf[tid] || (ov == sf[tid] && oi < si[tid])) { sf[tid] = ov; si[tid] = oi; }
        }
        __syncthreads();
    }
    if (tid == 0) g_midx[32 + c] = si[0];
}

// ---------------- gather selected boxes ----------------
__global__ void boxes_kernel(const float* __restrict__ ss) {
    int t = threadIdx.x;
    if (t < 2 * C_CLS) {
        int s = t / C_CLS, c = t % C_CLS;
        int idx = g_midx[s * 32 + c];
        float x1 = ss[idx * 5 + 1], y1 = ss[idx * 5 + 2];
        float x2 = ss[idx * 5 + 3], y2 = ss[idx * 5 + 4];
        float* b = g_boxes + t * 5;
        b[0] = x1; b[1] = y1; b[2] = x2; b[3] = y2;
        b[4] = (x2 - x1 + 1.f) * (y2 - y1 + 1.f);
    }
}

// ---------------- IoU supervision + loss partials ----------------
__global__ void suploss_kernel(const float* __restrict__ ss, const float* __restrict__ ISw,
                               const int* __restrict__ lab) {
    __shared__ float sb[2 * C_CLS * 5];
    __shared__ int   sl[C_CLS];
    __shared__ float red[256];
    int tid = threadIdx.x;
    if (tid < 2 * C_CLS * 5) sb[tid] = g_boxes[tid];
    if (tid < C_CLS)         sl[tid] = lab[tid];
    __syncthreads();

    int n = blockIdx.x * 256 + tid;
    float bx1 = ss[n * 5 + 1], by1 = ss[n * 5 + 2];
    float bx2 = ss[n * 5 + 3], by2 = ss[n * 5 + 4];
    float ab = (bx2 - bx1 + 1.f) * (by2 - by1 + 1.f);
    float w  = ISw[n];
    float res[4];
#pragma unroll
    for (int s = 0; s < 2; s++) {
        float mo = -1e30f; int gt = 0;
#pragma unroll
        for (int c = 0; c < C_CLS; c++) {
            const float* q = sb + (s * C_CLS + c) * 5;
            float ix1 = fmaxf(bx1, q[0]), iy1 = fmaxf(by1, q[1]);
            float ix2 = fminf(bx2, q[2]), iy2 = fminf(by2, q[3]);
            float iw = fmaxf(ix2 - ix1 + 1.f, 0.f), ih = fmaxf(iy2 - iy1 + 1.f, 0.f);
            float inter = iw * ih;
            float ov = (sl[c] == 1) ? inter / (ab + q[4] - inter) : -1.f;
            if (ov > mo) { mo = ov; gt = c; }
        }
        bool fg = mo > 0.5f;
        bool bg = (mo >= 0.1f) && (mo < 0.5f);
        bool keep = fg || bg;
        int col = fg ? gt + 1 : 0;
        int base = (s == 0) ? 20 : 41;   // refine_prob_1 / refine_prob_2
        float lp = logf(g_P[(size_t)n * 64 + base + col]);
        res[s * 2]     = keep ? 1.f : 0.f;
        res[s * 2 + 1] = keep ? w * lp : 0.f;
    }
#pragma unroll
    for (int j = 0; j < 4; j++) {
        red[tid] = res[j]; __syncthreads();
        for (int st = 128; st; st >>= 1) { if (tid < st) red[tid] += red[tid + st]; __syncthreads(); }
        if (tid == 0) g_part4[blockIdx.x * 4 + j] = red[0];
        __syncthreads();
    }
}

// ---------------- final combine ----------------
__global__ void final_kernel(const int* __restrict__ lab, float* __restrict__ out) {
    if (threadIdx.x != 0) return;
    float c1 = 0, s1 = 0, c2 = 0, s2 = 0;
    for (int b = 0; b < 16; b++) {
        c1 += g_part4[b * 4 + 0]; s1 += g_part4[b * 4 + 1];
        c2 += g_part4[b * 4 + 2]; s2 += g_part4[b * 4 + 3];
    }
    float h = 0.f;
    for (int c = 0; c < C_CLS; c++) h += fmaxf(0.f, 1.f - (float)lab[c] * g_dcs[c]);
    float loss = h / (float)C_CLS + 0.1f * (-s1 / c1) + 0.1f * (-s2 / c2);
    out[0] = loss;
}

// ---------------- launch ----------------
extern "C" void kernel_launch(void* const* d_in, const int* in_sizes, int n_in,
                              void* d_out, int out_size) {
    const float* roi = (const float*)d_in[0];
    const float* ctx = (const float*)d_in[1];
    const float* frm = (const float*)d_in[2];
    const float* Wc  = (const float*)d_in[3];
    const float* bc  = (const float*)d_in[4];
    const float* Wd  = (const float*)d_in[5];
    // d_in[6] = b_det: cancels analytically in det_score
    const float* W1  = (const float*)d_in[7];
    const float* b1  = (const float*)d_in[8];
    const float* W2  = (const float*)d_in[9];
    const float* b2  = (const float*)d_in[10];
    const float* ss  = (const float*)d_in[11];
    const float* isw = (const float*)d_in[12];
    const int*   lab = (const int*)d_in[13];
    float* out = (float*)d_out;

    pack_kernel<<<F_DIM, 64>>>(Wc, Wd, W1, W2, bc, b1, b2);
    gemm_tf32<64, false, true ><<<dim3(32, KSPLIT), 256>>>(roi, nullptr);
    gemm_tf32<32, true,  false><<<dim3(32, KSPLIT), 256>>>(frm, ctx);
    reduce_kernel<<<N_ROWS * 64 / 256, 256>>>();
    rowsoft_kernel<<<16, 256>>>();
    colstats_kernel<<<C_CLS, 256>>>(isw);
    boxes_kernel<<<1, 64>>>(ss);
    suploss_kernel<<<16, 256>>>(ss, isw, lab);
    final_kernel<<<1, 32>>>(lab, out);
}